// round 9
// baseline (speedup 1.0000x reference)
#include <cuda_runtime.h>
#include <cuda_bf16.h>
#include <cstdint>

// ---------------------------------------------------------------------------
// StackRNN v9: two-kernel split.
//  K1 (recurrence): 128 CTAs x 8 warps. Per step: state/mem logits + softmax
//     (unnormalized + Z partials), lagged stack update, ONE __syncthreads.
//     Streams raw exps/top/Z-partials per step to g_X[row=(b,t)][104].
//  K2 (buffer logits): tf32 tensor-core GEMM (3-term hi/lo split) of
//     X[262144 x 80] @ W[80 x 128] + E-table epilogue.
// Columns (N=210): [0,64) state, [64,82) mem-action, [82,210) buffer.
// Precompute: E (bias-FOLDED), CW, c.
// ---------------------------------------------------------------------------

#define NOUT 210
#define B_TOT 256
#define SEQ 1024
#define XROW 104
#define XPITCH 1025

typedef unsigned long long ull;

__device__ __forceinline__ ull ffma2(ull a, ull b, ull c) {
    ull d; asm("fma.rn.f32x2 %0,%1,%2,%3;" : "=l"(d) : "l"(a), "l"(b), "l"(c)); return d;
}
__device__ __forceinline__ ull fadd2(ull a, ull b) {
    ull d; asm("add.rn.f32x2 %0,%1,%2;" : "=l"(d) : "l"(a), "l"(b)); return d;
}
__device__ __forceinline__ ull pack2(float lo, float hi) {
    ull d; asm("mov.b64 %0,{%1,%2};" : "=l"(d) : "f"(lo), "f"(hi)); return d;
}
__device__ __forceinline__ float lo2(ull v) { return __uint_as_float((unsigned)v); }
__device__ __forceinline__ float hi2(ull v) { return __uint_as_float((unsigned)(v >> 32)); }

__device__ __align__(16) float g_E[128 * NOUT];    // bias folded in
__device__ __align__(16) float g_CW[80 * NOUT];
__device__ __align__(16) float g_c[NOUT];
__device__ float g_X[(size_t)B_TOT * XPITCH * XROW];   // per-(b,t) raw state

__global__ void precompute_kernel(
    const float* __restrict__ embed,
    const float* __restrict__ w_state, const float* __restrict__ b_state,
    const float* __restrict__ w_top,   const float* __restrict__ b_top,
    const float* __restrict__ w_mem,   const float* __restrict__ b_mem,
    const float* __restrict__ w_buf,   const float* __restrict__ b_buf,
    const float* __restrict__ w_st,    const float* __restrict__ b_st)
{
    __shared__ float wcol[768];
    __shared__ float cshare;
    int n = blockIdx.x;
    const float* W; const float* bias; int N, col;
    if (n < 64)       { W = w_st;  bias = b_st;  N = 64;  col = n; }
    else if (n < 82)  { W = w_mem; bias = b_mem; N = 18;  col = n - 64; }
    else              { W = w_buf; bias = b_buf; N = 128; col = n - 82; }

    int tid = threadIdx.x;
    for (int i = tid; i < 768; i += 256) wcol[i] = W[i * N + col];
    __syncthreads();
    if (tid == 208) {                     // folded bias
        float s = bias[col];
        for (int h = 0; h < 256; h++) s += b_state[h] * wcol[256 + h];
        for (int h = 0; h < 256; h++) s += b_top[h]   * wcol[512 + h];
        g_c[n] = s;
        cshare = s;
    }
    __syncthreads();

    if (tid < 128) {                      // E rows (bias folded)
        const float* er = embed + tid * 256;
        float s = cshare;
        for (int h = 0; h < 256; h++) s += er[h] * wcol[h];
        g_E[tid * NOUT + n] = s;
    } else if (tid < 192) {
        int r = tid - 128;
        const float* wr = w_state + r * 256;
        float s = 0.f;
        for (int h = 0; h < 256; h++) s += wr[h] * wcol[256 + h];
        g_CW[r * NOUT + n] = s;
    } else if (tid < 208) {
        int r = tid - 192;
        const float* wr = w_top + r * 256;
        float s = 0.f;
        for (int h = 0; h < 256; h++) s += wr[h] * wcol[512 + h];
        g_CW[(64 + r) * NOUT + n] = s;
    }
}

// ========================= K1: recurrence =========================
// smem floats: sE1 @0 :128*82=10496 | sTok @10496 :2048 ints |
//   sStack @12544 :4096 | sSt @16640 :256 | sZs @16896 :64 |
//   sTop @16960 :64 | sZmP @17024 :32 | sPr @17056 :80   -> 17136
#define K1_SMEM_FLOATS 17136

__device__ __forceinline__ void stack_update(const float* pr, const float* zmp,
                                             const float* P, float* Q, int lane)
{
    float pe0 = pr[0], pe1 = pr[1];
    float4 za = *(const float4*)zmp;
    float4 zb = *(const float4*)(zmp + 4);
    float Zr = ((za.x + za.y) + (za.z + za.w)) + ((zb.x + zb.y) + (zb.z + zb.w));
    float iz = __fdividef(1.f, Zr);
    float ppop  = pe0 * iz;
    float pnoop = pe1 * iz;
    float ppush = (Zr - pe0 - pe1) * iz;
    const int c = lane & 3;
    const int d0 = (lane >> 2) * 8;
    float4 pv = ((const float4*)(pr + 4))[c];
    pv.x *= iz; pv.y *= iz; pv.z *= iz; pv.w *= iz;

    const float4* P4 = (const float4*)P;
    float4*       Q4 = (float4*)Q;
    float4 prev = (d0 == 0) ? make_float4(0.f, 0.f, 0.f, 0.f) : P4[(d0 - 1) * 4 + c];
    float4 cur  = P4[d0 * 4 + c];
#pragma unroll
    for (int i = 0; i < 8; i++) {
        int d = d0 + i;
        float4 nxt;
        if (d == 63) nxt = (c == 0) ? make_float4(1.f, 0.f, 0.f, 0.f)
                                    : make_float4(0.f, 0.f, 0.f, 0.f);
        else         nxt = P4[(d + 1) * 4 + c];
        float4 o;
        o.x = ppush * prev.x + ppop * nxt.x + pnoop * cur.x;
        o.y = ppush * prev.y + ppop * nxt.y + pnoop * cur.y;
        o.z = ppush * prev.z + ppop * nxt.z + pnoop * cur.z;
        o.w = ppush * prev.w + ppop * nxt.w + pnoop * cur.w;
        if (d == 0) { o.x += pv.x; o.y += pv.y; o.z += pv.z; o.w += pv.w; }
        Q4[d * 4 + c] = o;
        prev = cur; cur = nxt;
    }
}

__global__ __launch_bounds__(256, 1)
void stackrnn_rec(const int* __restrict__ x, float* __restrict__ out)
{
    extern __shared__ float sm[];
    float* sE1    = sm;
    int*   sTok   = (int*)(sm + 10496);
    float* sStack = sm + 12544;
    float* sSt    = sm + 16640;
    float* sZs    = sm + 16896;
    float* sTop   = sm + 16960;
    float* sZmP   = sm + 17024;
    float* sPr    = sm + 17056;

    const int tid  = threadIdx.x;
    const int wid  = tid >> 5;
    const int lane = tid & 31;
    const int b0   = blockIdx.x * 2;

    // ---- setup ----
    for (int i = tid; i < 128 * 82; i += 256) {
        int tok = i / 82, n = i % 82;
        sE1[i] = g_E[tok * NOUT + n];          // bias already folded
    }
    for (int i = tid; i < 2 * SEQ; i += 256) {
        int g = i >> 10, r = i & 1023;
        sTok[i] = x[(size_t)(b0 + g) * SEQ + r];
    }
    for (int i = tid; i < 4096; i += 256) sStack[i] = ((i & 15) == 0 && i < 2048) ? 1.f : 0.f;
    if (tid < 128) sSt[tid] = 0.f;
    if (tid < 32)  sZs[tid]  = 0.0625f;
    if (tid < 32)  sTop[tid] = (tid == 0 || tid == 16) ? 1.f : 0.f;
    if (tid < 16)  sZmP[tid] = (tid == 0 || tid == 8) ? 1.f : 0.f;
    if (tid < 40)  sPr[tid]  = (tid == 1 || tid == 21) ? 1.f : 0.f;   // noop=1
    if (tid < 208) {                                  // g_X row 0 for both g
        int gg = tid / XROW, j = tid % XROW;
        float v = (j == 64 || j == 96) ? 1.f
                : (j >= 80 && j < 96)  ? 0.0625f : 0.f;
        g_X[((size_t)(b0 + gg) * XPITCH) * XROW + j] = v;
    }

    // ---- roles ----
    const bool isState  = (wid < 4);
    const bool isMem    = (wid == 4 || wid == 5);
    const bool isUpdate = (wid >= 6);
    int g, mycol;
    if (isState)       { g = wid >> 1;  mycol = (wid & 1) * 32 + lane; }
    else if (isMem)    { g = wid - 4;   mycol = 64 + (lane < 18 ? lane : 0); }
    else               { g = wid - 6;   mycol = 0; }

    ull W[40];
    if (!isUpdate) {
#pragma unroll
        for (int k = 0; k < 40; k++)
            W[k] = pack2(g_CW[(2 * k) * NOUT + mycol], g_CW[(2 * k + 1) * NOUT + mycol]);
    }
    __syncthreads();

    // mem-warp carried regs (lanes 0..15 = vocab v)
    float h0 = 0.f, h1 = 0.f, h2 = 0.f;
    float topc = 0.f;
    float cE0 = 0.f, cE1 = 1.f;
    if (isMem && lane == 0) { h0 = h1 = h2 = 1.f; topc = 1.f; }

    float baseNext = 0.f;
    if (!isUpdate) baseNext = sE1[sTok[g * SEQ] * 82 + mycol];

    for (int t = 0; t < SEQ; t++) {
        const int ping = t & 1;
        if (isUpdate) {
            stack_update(sPr + ping * 40 + g * 20, sZmP + ping * 16 + g * 8,
                         sStack + ping * 2048 + g * 1024,
                         sStack + (ping ^ 1) * 2048 + g * 1024, lane);
        } else {
            float izp = 0.f;
            if (isMem) {
                const float* zp = sZmP + ping * 16 + g * 8;
                float4 ma = *(const float4*)zp;
                float4 mb = *(const float4*)(zp + 4);
                float Zm = ((ma.x + ma.y) + (ma.z + ma.w)) +
                           ((mb.x + mb.y) + (mb.z + mb.w));
                izp = __fdividef(1.f, Zm);
                float nh0 = topc * izp;
                float nh1 = ((Zm - cE0 - cE1) * h0 + cE0 * h2 + cE1 * h1) * izp;
                float s1 = 0.f, s2 = 0.f, s3 = 0.f;
                const float* SB = sStack + ping * 2048 + g * 1024;
                if (lane < 16) { s1 = SB[16 + lane]; s2 = SB[32 + lane]; s3 = SB[48 + lane]; }
                float nh2 = ((Zm - cE0 - cE1) * s1 + cE0 * s3 + cE1 * s2) * izp;
                h0 = nh0; h1 = nh1; h2 = nh2;
            }

            const ulonglong2* ZS = (const ulonglong2*)(sZs + ping * 32 + g * 16);
            ulonglong2 z0 = ZS[0], z1 = ZS[1], z2 = ZS[2], z3 = ZS[3];
            ull zz = fadd2(fadd2(fadd2(z0.x, z0.y), fadd2(z1.x, z1.y)),
                           fadd2(fadd2(z2.x, z2.y), fadd2(z3.x, z3.y)));
            const float invZs = __fdividef(1.f, lo2(zz) + hi2(zz));
            float invZm;
            if (isMem) invZm = izp;
            else {
                const ulonglong2* ZM = (const ulonglong2*)(sZmP + ping * 16 + g * 8);
                ulonglong2 m0 = ZM[0], m1 = ZM[1];
                ull mm = fadd2(fadd2(m0.x, m0.y), fadd2(m1.x, m1.y));
                invZm = __fdividef(1.f, lo2(mm) + hi2(mm));
            }
            const float base = baseNext;

            const ulonglong2* S = (const ulonglong2*)(sSt + ping * 128 + g * 64);
            ull a0 = 0, a1 = 0, a2 = 0, a3 = 0;
#pragma unroll
            for (int i = 0; i < 8; i++) {
                ulonglong2 p = S[2 * i], q = S[2 * i + 1];
                a0 = ffma2(W[4 * i + 0], p.x, a0);
                a1 = ffma2(W[4 * i + 1], p.y, a1);
                a2 = ffma2(W[4 * i + 2], q.x, a2);
                a3 = ffma2(W[4 * i + 3], q.y, a3);
            }
            const ulonglong2* T = (const ulonglong2*)(sTop + ping * 32 + g * 16);
            ulonglong2 t0 = T[0], t1 = T[1], t2 = T[2], t3 = T[3];
            ull u0 = ffma2(W[32], t0.x, 0ULL), u1 = ffma2(W[33], t0.y, 0ULL);
            ull u2 = ffma2(W[34], t1.x, 0ULL), u3 = ffma2(W[35], t1.y, 0ULL);
            u0 = ffma2(W[36], t2.x, u0);  u1 = ffma2(W[37], t2.y, u1);
            u2 = ffma2(W[38], t3.x, u2);  u3 = ffma2(W[39], t3.y, u3);

            ull A = fadd2(fadd2(a0, a1), fadd2(a2, a3));
            ull U = fadd2(fadd2(u0, u1), fadd2(u2, u3));
            const float r = base + invZs * (lo2(A) + hi2(A)) + invZm * (lo2(U) + hi2(U));

            if (t + 1 < SEQ)
                baseNext = sE1[sTok[g * SEQ + t + 1] * 82 + mycol];

            const size_t xrow = ((size_t)(b0 + g) * XPITCH + (t + 1)) * XROW;
            if (isState) {
                float e = __expf(r);
                sSt[(ping ^ 1) * 128 + g * 64 + mycol] = e;
                g_X[xrow + mycol] = e;
                float ps = e;
                ps += __shfl_xor_sync(0xffffffffu, ps, 1);
                ps += __shfl_xor_sync(0xffffffffu, ps, 2);
                if ((lane & 3) == 0) {
                    int pi = (wid & 1) * 8 + (lane >> 2);
                    sZs[(ping ^ 1) * 32 + g * 16 + pi] = ps;
                    g_X[xrow + 80 + pi] = ps;
                }
            } else {  // mem
                float e = (lane < 18) ? __expf(r) : 0.f;
                float E0 = __shfl_sync(0xffffffffu, e, 0);
                float E1 = __shfl_sync(0xffffffffu, e, 1);
                float ep = __shfl_sync(0xffffffffu, e, 2 + (lane & 15));
                float topn = E1 * h0 + E0 * h1 + ep;     // raw, scale Zt
                if (lane < 16) {
                    sTop[(ping ^ 1) * 32 + g * 16 + lane] = topn;
                    g_X[xrow + 64 + lane] = topn;
                }
                int pidx = (lane < 2) ? lane : lane + 2;
                if (lane < 18) sPr[(ping ^ 1) * 40 + g * 20 + pidx] = e;
                float pz = e;
                pz += __shfl_xor_sync(0xffffffffu, pz, 1);
                pz += __shfl_xor_sync(0xffffffffu, pz, 2);
                if ((lane & 3) == 0) {
                    sZmP[(ping ^ 1) * 16 + g * 8 + (lane >> 2)] = pz;
                    g_X[xrow + 96 + (lane >> 2)] = pz;
                }
                topc = topn; cE0 = E0; cE1 = E1;
            }
        }
        __syncthreads();
    }

    // epilogue: apply probs_{S-1} -> stack_S (indices 0 after even SEQ)
    if (isUpdate) {
        stack_update(sPr + 0 * 40 + g * 20, sZmP + 0 * 16 + g * 8,
                     sStack + 0 * 2048 + g * 1024,
                     sStack + 1 * 2048 + g * 1024, lane);
    }
    __syncthreads();

    // finals
    const size_t fsOff = (size_t)B_TOT * SEQ * 128;
    const size_t stOff = fsOff + (size_t)B_TOT * 64 * 16;
    for (int i = tid; i < 2048; i += 256) {
        int gg = i >> 10, r = i & 1023;
        out[fsOff + (size_t)(b0 + gg) * 1024 + r] = sStack[2048 + i];
    }
    if (tid < 128) {
        int gg = tid >> 6;
        float zs = 0.f;
        for (int j = 0; j < 16; j++) zs += sZs[gg * 16 + j];
        out[stOff + (size_t)(b0 + gg) * 64 + (tid & 63)] =
            sSt[tid] * __fdividef(1.f, zs);
    }
}

// ========================= K2: buffer logits (tf32 MMA) =========================
#define MASK_TF32 0xFFFFE000u
// smem floats: sXh@0:10752 sXl@10752 sWh@21504:10880 sWl@32384 sTok@43264(ints 128)
#define K2_SMEM_BYTES ((43264 + 128) * 4)

__device__ __forceinline__ void mma_tf32(float* d,
    unsigned a0, unsigned a1, unsigned a2, unsigned a3,
    unsigned b0, unsigned b1)
{
    asm volatile(
        "mma.sync.aligned.m16n8k8.row.col.f32.tf32.tf32.f32 "
        "{%0,%1,%2,%3},{%4,%5,%6,%7},{%8,%9},{%0,%1,%2,%3};"
        : "+f"(d[0]), "+f"(d[1]), "+f"(d[2]), "+f"(d[3])
        : "r"(a0), "r"(a1), "r"(a2), "r"(a3), "r"(b0), "r"(b1));
}

__global__ __launch_bounds__(256, 1)
void stackrnn_buf(const int* __restrict__ x, float* __restrict__ out)
{
    extern __shared__ float s2[];
    float* sXh = s2;
    float* sXl = s2 + 10752;
    float* sWh = s2 + 21504;
    float* sWl = s2 + 32384;
    int*   sTk = (int*)(s2 + 43264);

    const int tid = threadIdx.x;
    const int b   = blockIdx.x >> 3;
    const int t0  = (blockIdx.x & 7) << 7;

    if (tid < 128) {
        int r = tid;
        const float* Xr = g_X + ((size_t)b * XPITCH + t0 + r) * XROW;
        float zs = 0.f, zm = 0.f;
#pragma unroll
        for (int j = 0; j < 16; j++) zs += Xr[80 + j];
#pragma unroll
        for (int j = 0; j < 8; j++)  zm += Xr[96 + j];
        float is = __fdividef(1.f, zs), im = __fdividef(1.f, zm);
#pragma unroll
        for (int j = 0; j < 80; j++) {
            float v = Xr[j] * (j < 64 ? is : im);
            unsigned hb = __float_as_uint(v) & MASK_TF32;
            float hf = __uint_as_float(hb);
            sXh[r * 84 + j] = hf;
            sXl[r * 84 + j] = __uint_as_float(__float_as_uint(v - hf) & MASK_TF32);
        }
        sTk[r] = x[(size_t)b * SEQ + t0 + r];
    } else {
        for (int i = tid - 128; i < 80 * 128; i += 128) {
            int k = i >> 7, n = i & 127;
            float v = g_CW[k * NOUT + 82 + n];
            unsigned hb = __float_as_uint(v) & MASK_TF32;
            float hf = __uint_as_float(hb);
            sWh[k * 136 + n] = hf;
            sWl[k * 136 + n] = __uint_as_float(__float_as_uint(v - hf) & MASK_TF32);
        }
    }
    __syncthreads();

    const int w = tid >> 5, lane = tid & 31;
    const int gi = lane >> 2, ti = lane & 3;
    const int m0 = w * 16;

    float acc[64];
#pragma unroll
    for (int i = 0; i < 64; i++) acc[i] = 0.f;

#pragma unroll
    for (int kt = 0; kt < 10; kt++) {
        int kb = kt * 8;
        unsigned ah0 = __float_as_uint(sXh[(m0 + gi)     * 84 + kb + ti]);
        unsigned ah1 = __float_as_uint(sXh[(m0 + 8 + gi) * 84 + kb + ti]);
        unsigned ah2 = __float_as_uint(sXh[(m0 + gi)     * 84 + kb + 4 + ti]);
        unsigned ah3 = __float_as_uint(sXh[(m0 + 8 + gi) * 84 + kb + 4 + ti]);
        unsigned al0 = __float_as_uint(sXl[(m0 + gi)     * 84 + kb + ti]);
        unsigned al1 = __float_as_uint(sXl[(m0 + 8 + gi) * 84 + kb + ti]);
        unsigned al2 = __float_as_uint(sXl[(m0 + gi)     * 84 + kb + 4 + ti]);
        unsigned al3 = __float_as_uint(sXl[(m0 + 8 + gi) * 84 + kb + 4 + ti]);
#pragma unroll
        for (int nt = 0; nt < 16; nt++) {
            int nb = nt * 8;
            unsigned bh0 = __float_as_uint(sWh[(kb + ti)     * 136 + nb + gi]);
            unsigned bh1 = __float_as_uint(sWh[(kb + 4 + ti) * 136 + nb + gi]);
            unsigned bl0 = __float_as_uint(sWl[(kb + ti)     * 136 + nb + gi]);
            unsigned bl1 = __float_as_uint(sWl[(kb + 4 + ti) * 136 + nb + gi]);
            mma_tf32(acc + nt * 4, ah0, ah1, ah2, ah3, bh0, bh1);
            mma_tf32(acc + nt * 4, ah0, ah1, ah2, ah3, bl0, bl1);
            mma_tf32(acc + nt * 4, al0, al1, al2, al3, bh0, bh1);
        }
    }

    const int r0 = m0 + gi, r1 = r0 + 8;
    const int tok0 = sTk[r0] * NOUT, tok1 = sTk[r1] * NOUT;
    const size_t o0 = ((size_t)b * SEQ + t0 + r0) * 128;
    const size_t o1 = ((size_t)b * SEQ + t0 + r1) * 128;
#pragma unroll
    for (int nt = 0; nt < 16; nt++) {
        int c = nt * 8 + ti * 2;
        out[o0 + c]     = acc[nt * 4 + 0] + g_E[tok0 + 82 + c];
        out[o0 + c + 1] = acc[nt * 4 + 1] + g_E[tok0 + 83 + c];
        out[o1 + c]     = acc[nt * 4 + 2] + g_E[tok1 + 82 + c];
        out[o1 + c + 1] = acc[nt * 4 + 3] + g_E[tok1 + 83 + c];
    }
}

extern "C" void kernel_launch(void* const* d_in, const int* in_sizes, int n_in,
                              void* d_out, int out_size)
{
    const int*   x       = (const int*)  d_in[0];
    const float* embed   = (const float*)d_in[1];
    const float* w_state = (const float*)d_in[2];
    const float* b_state = (const float*)d_in[3];
    const float* w_top   = (const float*)d_in[4];
    const float* b_top   = (const float*)d_in[5];
    const float* w_mem   = (const float*)d_in[6];
    const float* b_mem   = (const float*)d_in[7];
    const float* w_buf   = (const float*)d_in[8];
    const float* b_buf   = (const float*)d_in[9];
    const float* w_st    = (const float*)d_in[10];
    const float* b_st    = (const float*)d_in[11];
    float* out = (float*)d_out;

    precompute_kernel<<<NOUT, 256>>>(embed, w_state, b_state, w_top, b_top,
                                     w_mem, b_mem, w_buf, b_buf, w_st, b_st);

    cudaFuncSetAttribute(stackrnn_rec,
                         cudaFuncAttributeMaxDynamicSharedMemorySize,
                         K1_SMEM_FLOATS * sizeof(float));
    stackrnn_rec<<<B_TOT / 2, 256, K1_SMEM_FLOATS * sizeof(float)>>>(x, out);

    cudaFuncSetAttribute(stackrnn_buf,
                         cudaFuncAttributeMaxDynamicSharedMemorySize,
                         K2_SMEM_BYTES);
    stackrnn_buf<<<B_TOT * 8, 256, K2_SMEM_BYTES>>>(x, out);
}

// round 10
// speedup vs baseline: 1.0281x; 1.0281x over previous
#include <cuda_runtime.h>
#include <cuda_bf16.h>
#include <cstdint>

// ---------------------------------------------------------------------------
// StackRNN v10: two-kernel split, producer-reduction-free recurrence.
//  K1 (recurrence): 128 CTAs x 8 warps (4 state + 2 mem + 2 update), one
//     128-thread per-batch barrier per step. Softmaxes stored as raw exps;
//     EVERY consumer derives Z itself (state-Z folded into the dot loads,
//     mem-Z summed from the 18 raw probs). Streams per-step raw state to
//     g_X for K2.
//  K2 (buffer logits): tf32 MMA 3-term split of X[262144x80]@W[80x128]
//     + E-table epilogue.
// ---------------------------------------------------------------------------

#define NOUT 210
#define B_TOT 256
#define SEQ 1024
#define XROW 104
#define XPITCH 1025

#define BAR_SYNC(id, cnt) asm volatile("bar.sync %0, %1;" :: "r"(id), "r"(cnt) : "memory")

typedef unsigned long long ull;

__device__ __forceinline__ ull ffma2(ull a, ull b, ull c) {
    ull d; asm("fma.rn.f32x2 %0,%1,%2,%3;" : "=l"(d) : "l"(a), "l"(b), "l"(c)); return d;
}
__device__ __forceinline__ ull fadd2(ull a, ull b) {
    ull d; asm("add.rn.f32x2 %0,%1,%2;" : "=l"(d) : "l"(a), "l"(b)); return d;
}
__device__ __forceinline__ ull pack2(float lo, float hi) {
    ull d; asm("mov.b64 %0,{%1,%2};" : "=l"(d) : "f"(lo), "f"(hi)); return d;
}
__device__ __forceinline__ float lo2(ull v) { return __uint_as_float((unsigned)v); }
__device__ __forceinline__ float hi2(ull v) { return __uint_as_float((unsigned)(v >> 32)); }

__device__ __align__(16) float g_E[128 * NOUT];    // bias folded in
__device__ __align__(16) float g_CW[80 * NOUT];
__device__ float g_X[(size_t)B_TOT * XPITCH * XROW];

// ========================= precompute (fast) =========================
__global__ void precompute_kernel(
    const float* __restrict__ embed,
    const float* __restrict__ w_state, const float* __restrict__ b_state,
    const float* __restrict__ w_top,   const float* __restrict__ b_top,
    const float* __restrict__ w_mem,   const float* __restrict__ b_mem,
    const float* __restrict__ w_buf,   const float* __restrict__ b_buf,
    const float* __restrict__ w_st,    const float* __restrict__ b_st)
{
    __shared__ float wcol[768];
    __shared__ float cshare;
    int n = blockIdx.x;
    const float* W; const float* bias; int N, col;
    if (n < 64)       { W = w_st;  bias = b_st;  N = 64;  col = n; }
    else if (n < 82)  { W = w_mem; bias = b_mem; N = 18;  col = n - 64; }
    else              { W = w_buf; bias = b_buf; N = 128; col = n - 82; }

    int tid = threadIdx.x;
    for (int i = tid; i < 768; i += 448) wcol[i] = W[i * N + col];
    __syncthreads();

    float s = 0.f;
    if (tid < 256) {                       // E rows, pair-split
        int row = tid >> 1, half = tid & 1;
        const float* er = embed + row * 256 + half * 128;
        const float* wc = wcol + half * 128;
        float s0 = 0.f, s1 = 0.f, s2 = 0.f, s3 = 0.f;
        for (int h = 0; h < 128; h += 4) {
            s0 += er[h]     * wc[h];
            s1 += er[h + 1] * wc[h + 1];
            s2 += er[h + 2] * wc[h + 2];
            s3 += er[h + 3] * wc[h + 3];
        }
        s = (s0 + s1) + (s2 + s3);
    } else if (tid < 384) {                // state rows of CW
        int r = (tid - 256) >> 1, half = tid & 1;
        const float* wr = w_state + r * 256 + half * 128;
        const float* wc = wcol + 256 + half * 128;
        float s0 = 0.f, s1 = 0.f, s2 = 0.f, s3 = 0.f;
        for (int h = 0; h < 128; h += 4) {
            s0 += wr[h]     * wc[h];
            s1 += wr[h + 1] * wc[h + 1];
            s2 += wr[h + 2] * wc[h + 2];
            s3 += wr[h + 3] * wc[h + 3];
        }
        s = (s0 + s1) + (s2 + s3);
    } else if (tid < 416) {                // top rows of CW
        int r = (tid - 384) >> 1, half = tid & 1;
        const float* wr = w_top + r * 256 + half * 128;
        const float* wc = wcol + 512 + half * 128;
        float s0 = 0.f, s1 = 0.f, s2 = 0.f, s3 = 0.f;
        for (int h = 0; h < 128; h += 4) {
            s0 += wr[h]     * wc[h];
            s1 += wr[h + 1] * wc[h + 1];
            s2 += wr[h + 2] * wc[h + 2];
            s3 += wr[h + 3] * wc[h + 3];
        }
        s = (s0 + s1) + (s2 + s3);
    } else {                               // bias warp (lanes 0..31)
        int lane = tid - 416;
        for (int j = 0; j < 16; j++) {
            int k = lane * 16 + j;
            float bv = (k < 256) ? b_state[k] : b_top[k - 256];
            s += bv * wcol[256 + k];
        }
    }
    float sp = s + __shfl_xor_sync(0xffffffffu, s, 1);
    if (tid >= 416) {
        float t = s;
        for (int o = 16; o; o >>= 1) t += __shfl_xor_sync(0xffffffffu, t, o);
        if (tid == 416) cshare = t + bias[col];
    }
    __syncthreads();
    if (tid < 256)      { if ((tid & 1) == 0) g_E[(tid >> 1) * NOUT + n] = sp + cshare; }
    else if (tid < 384) { if ((tid & 1) == 0) g_CW[((tid - 256) >> 1) * NOUT + n] = sp; }
    else if (tid < 416) { if ((tid & 1) == 0) g_CW[(64 + ((tid - 384) >> 1)) * NOUT + n] = sp; }
}

// ========================= K1: recurrence =========================
// smem floats: sE1 @0:10496 | sTok @10496:2048 ints | sStack @12544:4096 |
//   sSt @16640:[ping][g][64]=256 | sTop @16896:[ping][g][16]=64 |
//   sPr @16960:[ping][g][20]=80  -> 17040
#define K1_SMEM_FLOATS 17040

// Zm = e_pop + e_noop + sum(e_push) from a raw-prob row (20 floats)
__device__ __forceinline__ float prob_row_sum(const float* pr, float2& ab_out)
{
    float2 ab = *(const float2*)pr;
    float4 q0 = *(const float4*)(pr + 4);
    float4 q1 = *(const float4*)(pr + 8);
    float4 q2 = *(const float4*)(pr + 12);
    float4 q3 = *(const float4*)(pr + 16);
    ab_out = ab;
    return ((ab.x + ab.y) + ((q0.x + q0.y) + (q0.z + q0.w)))
         + (((q1.x + q1.y) + (q1.z + q1.w)) + ((q2.x + q2.y) + (q2.z + q2.w)))
         + ((q3.x + q3.y) + (q3.z + q3.w));
}

__device__ __forceinline__ void stack_update(const float* pr,
                                             const float* P, float* Q, int lane)
{
    float2 ab;
    float Zr = prob_row_sum(pr, ab);
    float iz = __fdividef(1.f, Zr);
    float ppop  = ab.x * iz;
    float pnoop = ab.y * iz;
    float ppush = (Zr - ab.x - ab.y) * iz;
    const int c = lane & 3;
    const int d0 = (lane >> 2) * 8;
    float4 pv = ((const float4*)(pr + 4))[c];
    pv.x *= iz; pv.y *= iz; pv.z *= iz; pv.w *= iz;

    const float4* P4 = (const float4*)P;
    float4*       Q4 = (float4*)Q;
    float4 prev = (d0 == 0) ? make_float4(0.f, 0.f, 0.f, 0.f) : P4[(d0 - 1) * 4 + c];
    float4 cur  = P4[d0 * 4 + c];
#pragma unroll
    for (int i = 0; i < 8; i++) {
        int d = d0 + i;
        float4 nxt;
        if (d == 63) nxt = (c == 0) ? make_float4(1.f, 0.f, 0.f, 0.f)
                                    : make_float4(0.f, 0.f, 0.f, 0.f);
        else         nxt = P4[(d + 1) * 4 + c];
        float4 o;
        o.x = ppush * prev.x + ppop * nxt.x + pnoop * cur.x;
        o.y = ppush * prev.y + ppop * nxt.y + pnoop * cur.y;
        o.z = ppush * prev.z + ppop * nxt.z + pnoop * cur.z;
        o.w = ppush * prev.w + ppop * nxt.w + pnoop * cur.w;
        if (d == 0) { o.x += pv.x; o.y += pv.y; o.z += pv.z; o.w += pv.w; }
        Q4[d * 4 + c] = o;
        prev = cur; cur = nxt;
    }
}

__global__ __launch_bounds__(256, 1)
void stackrnn_rec(const int* __restrict__ x, float* __restrict__ out)
{
    extern __shared__ float sm[];
    float* sE1    = sm;
    int*   sTok   = (int*)(sm + 10496);
    float* sStack = sm + 12544;
    float* sSt    = sm + 16640;
    float* sTop   = sm + 16896;
    float* sPr    = sm + 16960;

    const int tid  = threadIdx.x;
    const int wid  = tid >> 5;
    const int lane = tid & 31;
    const int b0   = blockIdx.x * 2;

    // ---- setup ----
    for (int i = tid; i < 128 * 82; i += 256) {
        int tok = i / 82, n = i % 82;
        sE1[i] = g_E[tok * NOUT + n];
    }
    for (int i = tid; i < 2 * SEQ; i += 256) {
        int g = i >> 10, r = i & 1023;
        sTok[i] = x[(size_t)(b0 + g) * SEQ + r];
    }
    for (int i = tid; i < 4096; i += 256) sStack[i] = ((i & 15) == 0 && i < 2048) ? 1.f : 0.f;
    if (tid < 256) sSt[tid] = 0.f;
    if (tid < 32)  sTop[tid] = (tid == 0 || tid == 16) ? 1.f : 0.f;
    if (tid < 40)  sPr[tid]  = (tid == 1 || tid == 21) ? 1.f : 0.f;   // noop=1
    if (tid < 208) {                                  // g_X row 0 for both g
        int gg = tid / XROW, j = tid % XROW;
        g_X[((size_t)(b0 + gg) * XPITCH) * XROW + j] = (j == 64 || j == 81) ? 1.f : 0.f;
    }

    // ---- roles ----
    const bool isState  = (wid < 4);
    const bool isMem    = (wid == 4 || wid == 5);
    const bool isUpdate = (wid >= 6);
    int g, mycol;
    if (isState)       { g = wid >> 1;  mycol = (wid & 1) * 32 + lane; }
    else if (isMem)    { g = wid - 4;   mycol = 64 + (lane < 18 ? lane : 0); }
    else               { g = wid - 6;   mycol = 0; }
    const int barId = 1 + g;

    ull W[40];
    if (!isUpdate) {
#pragma unroll
        for (int k = 0; k < 40; k++)
            W[k] = pack2(g_CW[(2 * k) * NOUT + mycol], g_CW[(2 * k + 1) * NOUT + mycol]);
    }
    __syncthreads();

    // mem-warp carried regs (lanes 0..15 = vocab v)
    float h0 = 0.f, h1 = 0.f, h2 = 0.f;
    float topc = 0.f;
    if (isMem && lane == 0) { h0 = h1 = h2 = 1.f; topc = 1.f; }

    float baseNext = 0.f;
    if (!isUpdate) baseNext = sE1[sTok[g * SEQ] * 82 + mycol];

    for (int t = 0; t < SEQ; t++) {
        const int ping = t & 1;
        const float* pr = sPr + ping * 40 + g * 20;
        if (isUpdate) {
            stack_update(pr, sStack + ping * 2048 + g * 1024,
                         sStack + (ping ^ 1) * 2048 + g * 1024, lane);
        } else {
            // Zm of probs_{t-1} from raw probs (every consumer derives it)
            float2 ab;
            float zmv = prob_row_sum(pr, ab);
            const float invZm = __fdividef(1.f, zmv);

            // mem pre-dot: head rows normalized with invZm (probs_{t-1}'s Z)
            if (isMem) {
                float nh0 = topc * invZm;
                float nh1 = ((zmv - ab.x - ab.y) * h0 + ab.x * h2 + ab.y * h1) * invZm;
                float s1 = 0.f, s2 = 0.f, s3 = 0.f;
                const float* SB = sStack + ping * 2048 + g * 1024;
                if (lane < 16) { s1 = SB[16 + lane]; s2 = SB[32 + lane]; s3 = SB[48 + lane]; }
                float nh2 = ((zmv - ab.x - ab.y) * s1 + ab.x * s3 + ab.y * s2) * invZm;
                h0 = nh0; h1 = nh1; h2 = nh2;
            }

            // dot with state-Z folded into the same loads
            const ulonglong2* S = (const ulonglong2*)(sSt + ping * 128 + g * 64);
            ull a0 = 0, a1 = 0, a2 = 0, a3 = 0;
            ull z0 = 0, z1 = 0, z2 = 0, z3 = 0;
#pragma unroll
            for (int i = 0; i < 8; i++) {
                ulonglong2 p = S[2 * i], q = S[2 * i + 1];
                a0 = ffma2(W[4 * i + 0], p.x, a0);  z0 = fadd2(z0, p.x);
                a1 = ffma2(W[4 * i + 1], p.y, a1);  z1 = fadd2(z1, p.y);
                a2 = ffma2(W[4 * i + 2], q.x, a2);  z2 = fadd2(z2, q.x);
                a3 = ffma2(W[4 * i + 3], q.y, a3);  z3 = fadd2(z3, q.y);
            }
            ull zz = fadd2(fadd2(z0, z1), fadd2(z2, z3));
            const float invZs = __fdividef(1.f, fmaxf(lo2(zz) + hi2(zz), 1e-30f));

            const ulonglong2* T = (const ulonglong2*)(sTop + ping * 32 + g * 16);
            ulonglong2 t0 = T[0], t1 = T[1], t2 = T[2], t3 = T[3];
            ull u0 = ffma2(W[32], t0.x, 0ULL), u1 = ffma2(W[33], t0.y, 0ULL);
            ull u2 = ffma2(W[34], t1.x, 0ULL), u3 = ffma2(W[35], t1.y, 0ULL);
            u0 = ffma2(W[36], t2.x, u0);  u1 = ffma2(W[37], t2.y, u1);
            u2 = ffma2(W[38], t3.x, u2);  u3 = ffma2(W[39], t3.y, u3);

            ull A = fadd2(fadd2(a0, a1), fadd2(a2, a3));
            ull U = fadd2(fadd2(u0, u1), fadd2(u2, u3));
            const float r = baseNext + invZs * (lo2(A) + hi2(A)) + invZm * (lo2(U) + hi2(U));

            if (t + 1 < SEQ)
                baseNext = sE1[sTok[g * SEQ + t + 1] * 82 + mycol];

            const size_t xrow = ((size_t)(b0 + g) * XPITCH + (t + 1)) * XROW;
            if (isState) {
                float e = __expf(r);
                sSt[(ping ^ 1) * 128 + g * 64 + mycol] = e;
                g_X[xrow + mycol] = e;
            } else {  // mem
                float e = (lane < 18) ? __expf(r) : 0.f;
                float E0 = __shfl_sync(0xffffffffu, e, 0);
                float E1 = __shfl_sync(0xffffffffu, e, 1);
                float ep = __shfl_sync(0xffffffffu, e, 2 + (lane & 15));
                float topn = E1 * h0 + E0 * h1 + ep;     // raw, scale Zt
                if (lane < 16) {
                    sTop[(ping ^ 1) * 32 + g * 16 + lane] = topn;
                    g_X[xrow + 64 + lane] = topn;
                }
                int pidx = (lane < 2) ? lane : lane + 2;
                if (lane < 18) {
                    sPr[(ping ^ 1) * 40 + g * 20 + pidx] = e;
                    g_X[xrow + 80 + pidx] = e;
                }
                topc = topn;
            }
        }
        BAR_SYNC(barId, 128);
    }

    // epilogue: apply probs_{S-1} (sPr ping 0) -> stack_S
    if (isUpdate) {
        stack_update(sPr + 0 * 40 + g * 20,
                     sStack + 0 * 2048 + g * 1024,
                     sStack + 1 * 2048 + g * 1024, lane);
    }
    __syncthreads();

    // finals
    const size_t fsOff = (size_t)B_TOT * SEQ * 128;
    const size_t stOff = fsOff + (size_t)B_TOT * 64 * 16;
    for (int i = tid; i < 2048; i += 256) {
        int gg = i >> 10, r = i & 1023;
        out[fsOff + (size_t)(b0 + gg) * 1024 + r] = sStack[2048 + i];
    }
    if (tid < 128) {
        int gg = tid >> 6;
        float zs = 0.f;
        for (int j = 0; j < 64; j++) zs += sSt[gg * 64 + j];   // ping 0 = final
        out[stOff + (size_t)(b0 + gg) * 64 + (tid & 63)] =
            sSt[tid] * __fdividef(1.f, fmaxf(zs, 1e-30f));
    }
}

// ========================= K2: buffer logits (tf32 MMA) =========================
#define MASK_TF32 0xFFFFE000u
#define K2_SMEM_BYTES ((43264 + 128) * 4)

__device__ __forceinline__ void mma_tf32(float* d,
    unsigned a0, unsigned a1, unsigned a2, unsigned a3,
    unsigned b0, unsigned b1)
{
    asm volatile(
        "mma.sync.aligned.m16n8k8.row.col.f32.tf32.tf32.f32 "
        "{%0,%1,%2,%3},{%4,%5,%6,%7},{%8,%9},{%0,%1,%2,%3};"
        : "+f"(d[0]), "+f"(d[1]), "+f"(d[2]), "+f"(d[3])
        : "r"(a0), "r"(a1), "r"(a2), "r"(a3), "r"(b0), "r"(b1));
}

__global__ __launch_bounds__(256, 1)
void stackrnn_buf(const int* __restrict__ x, float* __restrict__ out)
{
    extern __shared__ float s2[];
    float* sXh = s2;
    float* sXl = s2 + 10752;
    float* sWh = s2 + 21504;
    float* sWl = s2 + 32384;
    int*   sTk = (int*)(s2 + 43264);

    const int tid = threadIdx.x;
    const int b   = blockIdx.x >> 3;
    const int t0  = (blockIdx.x & 7) << 7;

    if (tid < 128) {
        int r = tid;
        const float* Xr = g_X + ((size_t)b * XPITCH + t0 + r) * XROW;
        float zs = 0.f, zm = 0.f;
#pragma unroll
        for (int j = 0; j < 64; j++) zs += Xr[j];
        zm = Xr[80] + Xr[81];
#pragma unroll
        for (int j = 84; j < 100; j++) zm += Xr[j];
        float is = __fdividef(1.f, fmaxf(zs, 1e-30f));
        float im = __fdividef(1.f, zm);
#pragma unroll
        for (int j = 0; j < 80; j++) {
            float v = Xr[j] * (j < 64 ? is : im);
            unsigned hb = __float_as_uint(v) & MASK_TF32;
            float hf = __uint_as_float(hb);
            sXh[r * 84 + j] = hf;
            sXl[r * 84 + j] = __uint_as_float(__float_as_uint(v - hf) & MASK_TF32);
        }
        sTk[r] = x[(size_t)b * SEQ + t0 + r];
    } else {
        for (int i = tid - 128; i < 80 * 128; i += 128) {
            int k = i >> 7, n = i & 127;
            float v = g_CW[k * NOUT + 82 + n];
            unsigned hb = __float_as_uint(v) & MASK_TF32;
            float hf = __uint_as_float(hb);
            sWh[k * 136 + n] = hf;
            sWl[k * 136 + n] = __uint_as_float(__float_as_uint(v - hf) & MASK_TF32);
        }
    }
    __syncthreads();

    const int w = tid >> 5, lane = tid & 31;
    const int gi = lane >> 2, ti = lane & 3;
    const int m0 = w * 16;

    float acc[64];
#pragma unroll
    for (int i = 0; i < 64; i++) acc[i] = 0.f;

#pragma unroll
    for (int kt = 0; kt < 10; kt++) {
        int kb = kt * 8;
        unsigned ah0 = __float_as_uint(sXh[(m0 + gi)     * 84 + kb + ti]);
        unsigned ah1 = __float_as_uint(sXh[(m0 + 8 + gi) * 84 + kb + ti]);
        unsigned ah2 = __float_as_uint(sXh[(m0 + gi)     * 84 + kb + 4 + ti]);
        unsigned ah3 = __float_as_uint(sXh[(m0 + 8 + gi) * 84 + kb + 4 + ti]);
        unsigned al0 = __float_as_uint(sXl[(m0 + gi)     * 84 + kb + ti]);
        unsigned al1 = __float_as_uint(sXl[(m0 + 8 + gi) * 84 + kb + ti]);
        unsigned al2 = __float_as_uint(sXl[(m0 + gi)     * 84 + kb + 4 + ti]);
        unsigned al3 = __float_as_uint(sXl[(m0 + 8 + gi) * 84 + kb + 4 + ti]);
#pragma unroll
        for (int nt = 0; nt < 16; nt++) {
            int nb = nt * 8;
            unsigned bh0 = __float_as_uint(sWh[(kb + ti)     * 136 + nb + gi]);
            unsigned bh1 = __float_as_uint(sWh[(kb + 4 + ti) * 136 + nb + gi]);
            unsigned bl0 = __float_as_uint(sWl[(kb + ti)     * 136 + nb + gi]);
            unsigned bl1 = __float_as_uint(sWl[(kb + 4 + ti) * 136 + nb + gi]);
            mma_tf32(acc + nt * 4, ah0, ah1, ah2, ah3, bh0, bh1);
            mma_tf32(acc + nt * 4, ah0, ah1, ah2, ah3, bl0, bl1);
            mma_tf32(acc + nt * 4, al0, al1, al2, al3, bh0, bh1);
        }
    }

    const int r0 = m0 + gi, r1 = r0 + 8;
    const int tok0 = sTk[r0] * NOUT, tok1 = sTk[r1] * NOUT;
    const size_t o0 = ((size_t)b * SEQ + t0 + r0) * 128;
    const size_t o1 = ((size_t)b * SEQ + t0 + r1) * 128;
#pragma unroll
    for (int nt = 0; nt < 16; nt++) {
        int c = nt * 8 + ti * 2;
        out[o0 + c]     = acc[nt * 4 + 0] + g_E[tok0 + 82 + c];
        out[o0 + c + 1] = acc[nt * 4 + 1] + g_E[tok0 + 83 + c];
        out[o1 + c]     = acc[nt * 4 + 2] + g_E[tok1 + 82 + c];
        out[o1 + c + 1] = acc[nt * 4 + 3] + g_E[tok1 + 83 + c];
    }
}

extern "C" void kernel_launch(void* const* d_in, const int* in_sizes, int n_in,
                              void* d_out, int out_size)
{
    const int*   x       = (const int*)  d_in[0];
    const float* embed   = (const float*)d_in[1];
    const float* w_state = (const float*)d_in[2];
    const float* b_state = (const float*)d_in[3];
    const float* w_top   = (const float*)d_in[4];
    const float* b_top   = (const float*)d_in[5];
    const float* w_mem   = (const float*)d_in[6];
    const float* b_mem   = (const float*)d_in[7];
    const float* w_buf   = (const float*)d_in[8];
    const float* b_buf   = (const float*)d_in[9];
    const float* w_st    = (const float*)d_in[10];
    const float* b_st    = (const float*)d_in[11];
    float* out = (float*)d_out;

    precompute_kernel<<<NOUT, 448>>>(embed, w_state, b_state, w_top, b_top,
                                     w_mem, b_mem, w_buf, b_buf, w_st, b_st);

    cudaFuncSetAttribute(stackrnn_rec,
                         cudaFuncAttributeMaxDynamicSharedMemorySize,
                         K1_SMEM_FLOATS * sizeof(float));
    stackrnn_rec<<<B_TOT / 2, 256, K1_SMEM_FLOATS * sizeof(float)>>>(x, out);

    cudaFuncSetAttribute(stackrnn_buf,
                         cudaFuncAttributeMaxDynamicSharedMemorySize,
                         K2_SMEM_BYTES);
    stackrnn_buf<<<B_TOT * 8, 256, K2_SMEM_BYTES>>>(x, out);
}

// round 12
// speedup vs baseline: 1.1517x; 1.1202x over previous
#include <cuda_runtime.h>
#include <cuda_bf16.h>
#include <cstdint>

// ---------------------------------------------------------------------------
// StackRNN v12 = v6 (best measured recurrence kernel, 725us) + vectorized
// precompute (float4 operand streams, row split across 2 threads) with the
// bias-warp indexing bug fixed (k = lane + j*32, NOT lane*4 + j*32).
//
// Group A (warps 0-7, 256 thr): 4 state + 2 mem + 2 update warps. One
//   bar.sync(1,256) per step. Writes per-step slots into a DEPTH-4 ring.
// Group B (warps 8-15, 256 thr): buffer-logit warps, lag <=3 steps behind.
//   Per slot s: ready barrier id 2+s (A arrives, B syncs), free id 6+s.
//
// Columns (N=210): [0,64) state logits, [64,82) mem-action, [82,210) buffer.
// Weights K-packed for f32x2 FFMA2. Softmaxes kept unnormalized with
// partial-sum Z folding. Stack update runs one step lagged.
// ---------------------------------------------------------------------------

#define NOUT 210
#define B_TOT 256
#define SEQ 1024
#define NTHREADS 512

#define BAR_SYNC(id, cnt)   asm volatile("bar.sync %0, %1;"   :: "r"(id), "r"(cnt) : "memory")
#define BAR_ARRIVE(id, cnt) asm volatile("bar.arrive %0, %1;" :: "r"(id), "r"(cnt) : "memory")

typedef unsigned long long ull;

__device__ __forceinline__ ull ffma2(ull a, ull b, ull c) {
    ull d; asm("fma.rn.f32x2 %0,%1,%2,%3;" : "=l"(d) : "l"(a), "l"(b), "l"(c)); return d;
}
__device__ __forceinline__ ull fadd2(ull a, ull b) {
    ull d; asm("add.rn.f32x2 %0,%1,%2;" : "=l"(d) : "l"(a), "l"(b)); return d;
}
__device__ __forceinline__ ull pack2(float lo, float hi) {
    ull d; asm("mov.b64 %0,{%1,%2};" : "=l"(d) : "f"(lo), "f"(hi)); return d;
}
__device__ __forceinline__ float lo2(ull v) { return __uint_as_float((unsigned)v); }
__device__ __forceinline__ float hi2(ull v) { return __uint_as_float((unsigned)(v >> 32)); }

__device__ __align__(16) float g_E[128 * NOUT];
__device__ __align__(16) float g_CW[80 * NOUT];
__device__ __align__(16) float g_c[NOUT];

// ---------------- fast precompute: float4 streams, 2 threads/row ----------------
__global__ void precompute_kernel(
    const float* __restrict__ embed,
    const float* __restrict__ w_state, const float* __restrict__ b_state,
    const float* __restrict__ w_top,   const float* __restrict__ b_top,
    const float* __restrict__ w_mem,   const float* __restrict__ b_mem,
    const float* __restrict__ w_buf,   const float* __restrict__ b_buf,
    const float* __restrict__ w_st,    const float* __restrict__ b_st)
{
    __shared__ __align__(16) float wcol[768];
    int n = blockIdx.x;
    const float* W; const float* bias; int N, col;
    if (n < 64)       { W = w_st;  bias = b_st;  N = 64;  col = n; }
    else if (n < 82)  { W = w_mem; bias = b_mem; N = 18;  col = n - 64; }
    else              { W = w_buf; bias = b_buf; N = 128; col = n - 82; }

    const int tid = threadIdx.x;
    for (int i = tid; i < 768; i += 448) wcol[i] = W[i * N + col];
    __syncthreads();

    float sp = 0.f;
    if (tid < 256) {                       // E rows: 2 threads per row
        int row = tid >> 1, half = tid & 1;
        const float4* er = (const float4*)(embed + row * 256 + half * 128);
        const float4* wc = (const float4*)(wcol + half * 128);
        float s0 = 0.f, s1 = 0.f, s2 = 0.f, s3 = 0.f;
#pragma unroll 8
        for (int h = 0; h < 32; h++) {
            float4 e = er[h], w4 = wc[h];
            s0 += e.x * w4.x; s1 += e.y * w4.y;
            s2 += e.z * w4.z; s3 += e.w * w4.w;
        }
        sp = (s0 + s1) + (s2 + s3);
    } else if (tid < 384) {                // state rows of CW
        int r = (tid - 256) >> 1, half = tid & 1;
        const float4* wr = (const float4*)(w_state + r * 256 + half * 128);
        const float4* wc = (const float4*)(wcol + 256 + half * 128);
        float s0 = 0.f, s1 = 0.f, s2 = 0.f, s3 = 0.f;
#pragma unroll 8
        for (int h = 0; h < 32; h++) {
            float4 e = wr[h], w4 = wc[h];
            s0 += e.x * w4.x; s1 += e.y * w4.y;
            s2 += e.z * w4.z; s3 += e.w * w4.w;
        }
        sp = (s0 + s1) + (s2 + s3);
    } else if (tid < 416) {                // top rows of CW
        int r = (tid - 384) >> 1, half = tid & 1;
        const float4* wr = (const float4*)(w_top + r * 256 + half * 128);
        const float4* wc = (const float4*)(wcol + 512 + half * 128);
        float s0 = 0.f, s1 = 0.f, s2 = 0.f, s3 = 0.f;
#pragma unroll 8
        for (int h = 0; h < 32; h++) {
            float4 e = wr[h], w4 = wc[h];
            s0 += e.x * w4.x; s1 += e.y * w4.y;
            s2 += e.z * w4.z; s3 += e.w * w4.w;
        }
        sp = (s0 + s1) + (s2 + s3);
    } else {                               // bias warp
        int lane = tid - 416;
        const float4* bs = (const float4*)b_state;
        const float4* bt = (const float4*)b_top;
        const float4* wc = (const float4*)(wcol + 256);
        // lane handles float4 indices {lane, lane+32, lane+64, lane+96}
        // across the 128-float4-long [b_state; b_top] stream.
#pragma unroll
        for (int j = 0; j < 4; j++) {
            int k = lane + j * 32;         // float4 index in [0,128)
            float4 b4 = (k < 64) ? bs[k] : bt[k - 64];
            float4 w4 = wc[k];
            sp += b4.x * w4.x + b4.y * w4.y + b4.z * w4.z + b4.w * w4.w;
        }
        float t = sp;
        for (int o = 16; o; o >>= 1) t += __shfl_xor_sync(0xffffffffu, t, o);
        if (lane == 0) g_c[n] = t + bias[col];
    }

    float pair = sp + __shfl_xor_sync(0xffffffffu, sp, 1);
    if ((tid & 1) == 0) {
        if (tid < 256)      g_E[(tid >> 1) * NOUT + n] = pair;
        else if (tid < 384) g_CW[((tid - 256) >> 1) * NOUT + n] = pair;
        else if (tid < 416) g_CW[(64 + ((tid - 384) >> 1)) * NOUT + n] = pair;
    }
}

// Shared floats:
//   sE     @ 0     : 26880            [tok][n]
//   sTok   @ 26880 : 2048 ints        [g][t]
//   sStack @ 28928 : [ping][g][64][16] = 4096   (depth 2, A-only)
//   sSt    @ 33024 : [slot][g][64] = 512        raw state exps (depth 4)
//   sZs    @ 33536 : [slot][g][16] = 128        state Z partials (depth 4)
//   sTop   @ 33664 : [slot][g][16] = 128        raw top~ (depth 4)
//   sZmP   @ 33792 : [slot][g][8]  = 64         mem Z partials (depth 4)
//   sPr    @ 33856 : [ping][g][20] = 80         raw probs (depth 2, A-only)
#define SMEM_FLOATS 33936

__device__ __forceinline__ void stack_update(const float* pr, const float* zmp,
                                             const float* P, float* Q, int lane)
{
    float pe0 = pr[0], pe1 = pr[1];
    float4 za = *(const float4*)zmp;
    float4 zb = *(const float4*)(zmp + 4);
    float Zr = ((za.x + za.y) + (za.z + za.w)) + ((zb.x + zb.y) + (zb.z + zb.w));
    float iz = __fdividef(1.f, Zr);
    float ppop  = pe0 * iz;
    float pnoop = pe1 * iz;
    float ppush = (Zr - pe0 - pe1) * iz;
    const int c = lane & 3;
    const int d0 = (lane >> 2) * 8;
    float4 pv = ((const float4*)(pr + 4))[c];
    pv.x *= iz; pv.y *= iz; pv.z *= iz; pv.w *= iz;

    const float4* P4 = (const float4*)P;
    float4*       Q4 = (float4*)Q;
    float4 prev = (d0 == 0) ? make_float4(0.f, 0.f, 0.f, 0.f) : P4[(d0 - 1) * 4 + c];
    float4 cur  = P4[d0 * 4 + c];
#pragma unroll
    for (int i = 0; i < 8; i++) {
        int d = d0 + i;
        float4 nxt;
        if (d == 63) nxt = (c == 0) ? make_float4(1.f, 0.f, 0.f, 0.f)
                                    : make_float4(0.f, 0.f, 0.f, 0.f);
        else         nxt = P4[(d + 1) * 4 + c];
        float4 o;
        o.x = ppush * prev.x + ppop * nxt.x + pnoop * cur.x;
        o.y = ppush * prev.y + ppop * nxt.y + pnoop * cur.y;
        o.z = ppush * prev.z + ppop * nxt.z + pnoop * cur.z;
        o.w = ppush * prev.w + ppop * nxt.w + pnoop * cur.w;
        if (d == 0) { o.x += pv.x; o.y += pv.y; o.z += pv.z; o.w += pv.w; }
        Q4[d * 4 + c] = o;
        prev = cur; cur = nxt;
    }
}

__global__ __launch_bounds__(NTHREADS, 1)
void stackrnn_kernel(const int* __restrict__ x, float* __restrict__ out)
{
    extern __shared__ float sm[];
    float* sE     = sm;
    int*   sTok   = (int*)(sm + 26880);
    float* sStack = sm + 28928;
    float* sSt    = sm + 33024;
    float* sZs    = sm + 33536;
    float* sTop   = sm + 33664;
    float* sZmP   = sm + 33792;
    float* sPr    = sm + 33856;

    const int tid  = threadIdx.x;
    const int wid  = tid >> 5;
    const int lane = tid & 31;
    const int b0   = blockIdx.x * 2;

    // ---- one-time setup ----
    {
        const float4* src = (const float4*)g_E;
        float4* dst = (float4*)sE;
        for (int i = tid; i < (128 * NOUT) / 4; i += NTHREADS) dst[i] = src[i];
    }
    for (int i = tid; i < 2 * SEQ; i += NTHREADS) {
        int g = i >> 10, r = i & 1023;
        sTok[i] = x[(size_t)(b0 + g) * SEQ + r];
    }
    for (int i = tid; i < 2048; i += NTHREADS) sStack[i] = ((i & 15) == 0) ? 1.f : 0.f;
    if (tid < 128) sSt[tid] = 0.f;                            // slot 0
    if (tid < 32)  sZs[tid]  = 0.0625f;                       // slot 0: sums to 1
    if (tid < 32)  sTop[tid] = (tid == 0 || tid == 16) ? 1.f : 0.f;
    if (tid < 16)  sZmP[tid] = (tid == 0 || tid == 8) ? 1.f : 0.f;
    if (tid < 40)  sPr[tid]  = (tid == 1 || tid == 21) ? 1.f : 0.f;  // noop=1

    // ---- roles ----
    const bool isState  = (wid < 4);
    const bool isMem    = (wid == 4 || wid == 5);
    const bool isUpdate = (wid == 6 || wid == 7);
    const bool isBuf    = (wid >= 8);
    int g, mycol;
    if (isState)       { g = wid >> 1;  mycol = (wid & 1) * 32 + lane; }
    else if (isMem)    { g = wid - 4;   mycol = 64 + (lane < 18 ? lane : 0); }
    else if (isUpdate) { g = wid - 6;   mycol = 0; }
    else               { int idx = tid - 256; g = idx >> 7; mycol = 82 + (idx & 127); }

    ull W[40];
    float cn = 0.f;
    if (!isUpdate) {
        cn = g_c[mycol];
#pragma unroll
        for (int k = 0; k < 40; k++)
            W[k] = pack2(g_CW[(2 * k) * NOUT + mycol], g_CW[(2 * k + 1) * NOUT + mycol]);
    }
    __syncthreads();

    if (isBuf) {
        // =================== GROUP B: buffer logits, lagged ===================
        const size_t outB = (size_t)(b0 + g) * (SEQ * 128);
        float baseNext = cn + sE[sTok[g * SEQ] * NOUT + mycol];
        for (int t = 0; t < SEQ; t++) {
            const int sCur = t & 3;
            BAR_SYNC(2 + sCur, 512);          // wait slot ready

            const ulonglong2* ZS = (const ulonglong2*)(sZs + sCur * 32 + g * 16);
            ulonglong2 z0 = ZS[0], z1 = ZS[1], z2 = ZS[2], z3 = ZS[3];
            ull zz = fadd2(fadd2(fadd2(z0.x, z0.y), fadd2(z1.x, z1.y)),
                           fadd2(fadd2(z2.x, z2.y), fadd2(z3.x, z3.y)));
            const float invZs = __fdividef(1.f, lo2(zz) + hi2(zz));
            const ulonglong2* ZM = (const ulonglong2*)(sZmP + sCur * 16 + g * 8);
            ulonglong2 m0 = ZM[0], m1 = ZM[1];
            ull mm = fadd2(fadd2(m0.x, m0.y), fadd2(m1.x, m1.y));
            const float invZm = __fdividef(1.f, lo2(mm) + hi2(mm));
            const float base = baseNext;

            const ulonglong2* S = (const ulonglong2*)(sSt + sCur * 128 + g * 64);
            ull a0 = 0, a1 = 0, a2 = 0, a3 = 0;
#pragma unroll
            for (int i = 0; i < 8; i++) {
                ulonglong2 p = S[2 * i], q = S[2 * i + 1];
                a0 = ffma2(W[4 * i + 0], p.x, a0);
                a1 = ffma2(W[4 * i + 1], p.y, a1);
                a2 = ffma2(W[4 * i + 2], q.x, a2);
                a3 = ffma2(W[4 * i + 3], q.y, a3);
            }
            const ulonglong2* T = (const ulonglong2*)(sTop + sCur * 32 + g * 16);
            ulonglong2 t0 = T[0], t1 = T[1], t2 = T[2], t3 = T[3];
            ull u0 = ffma2(W[32], t0.x, 0ULL), u1 = ffma2(W[33], t0.y, 0ULL);
            ull u2 = ffma2(W[34], t1.x, 0ULL), u3 = ffma2(W[35], t1.y, 0ULL);
            u0 = ffma2(W[36], t2.x, u0);  u1 = ffma2(W[37], t2.y, u1);
            u2 = ffma2(W[38], t3.x, u2);  u3 = ffma2(W[39], t3.y, u3);

            ull A = fadd2(fadd2(a0, a1), fadd2(a2, a3));
            ull U = fadd2(fadd2(u0, u1), fadd2(u2, u3));
            const float r = base + invZs * (lo2(A) + hi2(A)) + invZm * (lo2(U) + hi2(U));
            out[outB + (size_t)t * 128 + (mycol - 82)] = r;

            if (t + 1 < SEQ)
                baseNext = cn + sE[sTok[g * SEQ + t + 1] * NOUT + mycol];
            BAR_ARRIVE(6 + sCur, 512);        // release slot
        }
    } else {
        // =================== GROUP A: recurrence ===================
        // mem-warp carried regs (lanes 0..15 hold vocab component v=lane)
        float h0 = 0.f, h1 = 0.f, h2 = 0.f;      // normalized rows of current stack
        float topc = 0.f;                         // raw row0 of next stack
        float cE0 = 0.f, cE1 = 1.f, cZp = 0.125f; // probs_{-1}=noop; Z partial
        if (isMem && lane == 0) { h0 = h1 = h2 = 1.f; topc = 1.f; }

        float baseNext = 0.f;
        if (!isUpdate) baseNext = cn + sE[sTok[g * SEQ] * NOUT + mycol];

        BAR_ARRIVE(2 + 0, 512);                   // slot 0 (initial state) ready

        for (int t = 0; t < SEQ; t++) {
            const int sCur  = t & 3;
            const int sNext = (t + 1) & 3;
            const int ping  = t & 1;
            if (t >= 3) BAR_SYNC(6 + sNext, 512); // wait B freed the slot we rewrite

            if (isUpdate) {
                stack_update(sPr + ping * 40 + g * 20, sZmP + sCur * 16 + g * 8,
                             sStack + ping * 2048 + g * 1024,
                             sStack + (ping ^ 1) * 2048 + g * 1024, lane);
            } else {
                // mem pre-dot: finish deferred Z + head rows (overlaps dot loads)
                if (isMem) {
                    float Zp = cZp;
                    Zp += __shfl_xor_sync(0xffffffffu, Zp, 4);
                    Zp += __shfl_xor_sync(0xffffffffu, Zp, 8);
                    Zp += __shfl_xor_sync(0xffffffffu, Zp, 16);
                    float izp = __fdividef(1.f, Zp);
                    float nh0 = topc * izp;
                    float nh1 = ((Zp - cE0 - cE1) * h0 + cE0 * h2 + cE1 * h1) * izp;
                    float s1 = 0.f, s2 = 0.f, s3 = 0.f;
                    const float* SB = sStack + ping * 2048 + g * 1024;
                    if (lane < 16) { s1 = SB[16 + lane]; s2 = SB[32 + lane]; s3 = SB[48 + lane]; }
                    float nh2 = ((Zp - cE0 - cE1) * s1 + cE0 * s3 + cE1 * s2) * izp;
                    h0 = nh0; h1 = nh1; h2 = nh2;
                }

                const ulonglong2* ZS = (const ulonglong2*)(sZs + sCur * 32 + g * 16);
                ulonglong2 z0 = ZS[0], z1 = ZS[1], z2 = ZS[2], z3 = ZS[3];
                ull zz = fadd2(fadd2(fadd2(z0.x, z0.y), fadd2(z1.x, z1.y)),
                               fadd2(fadd2(z2.x, z2.y), fadd2(z3.x, z3.y)));
                const float invZs = __fdividef(1.f, lo2(zz) + hi2(zz));
                const ulonglong2* ZM = (const ulonglong2*)(sZmP + sCur * 16 + g * 8);
                ulonglong2 m0 = ZM[0], m1 = ZM[1];
                ull mm = fadd2(fadd2(m0.x, m0.y), fadd2(m1.x, m1.y));
                const float invZm = __fdividef(1.f, lo2(mm) + hi2(mm));
                const float base = baseNext;

                const ulonglong2* S = (const ulonglong2*)(sSt + sCur * 128 + g * 64);
                ull a0 = 0, a1 = 0, a2 = 0, a3 = 0;
#pragma unroll
                for (int i = 0; i < 8; i++) {
                    ulonglong2 p = S[2 * i], q = S[2 * i + 1];
                    a0 = ffma2(W[4 * i + 0], p.x, a0);
                    a1 = ffma2(W[4 * i + 1], p.y, a1);
                    a2 = ffma2(W[4 * i + 2], q.x, a2);
                    a3 = ffma2(W[4 * i + 3], q.y, a3);
                }
                const ulonglong2* T = (const ulonglong2*)(sTop + sCur * 32 + g * 16);
                ulonglong2 t0 = T[0], t1 = T[1], t2 = T[2], t3 = T[3];
                ull u0 = ffma2(W[32], t0.x, 0ULL), u1 = ffma2(W[33], t0.y, 0ULL);
                ull u2 = ffma2(W[34], t1.x, 0ULL), u3 = ffma2(W[35], t1.y, 0ULL);
                u0 = ffma2(W[36], t2.x, u0);  u1 = ffma2(W[37], t2.y, u1);
                u2 = ffma2(W[38], t3.x, u2);  u3 = ffma2(W[39], t3.y, u3);

                ull A = fadd2(fadd2(a0, a1), fadd2(a2, a3));
                ull U = fadd2(fadd2(u0, u1), fadd2(u2, u3));
                const float r = base + invZs * (lo2(A) + hi2(A)) + invZm * (lo2(U) + hi2(U));

                if (t + 1 < SEQ)
                    baseNext = cn + sE[sTok[g * SEQ + t + 1] * NOUT + mycol];

                if (isState) {
                    float e = __expf(r);
                    sSt[sNext * 128 + g * 64 + mycol] = e;
                    float ps = e;
                    ps += __shfl_xor_sync(0xffffffffu, ps, 1);
                    ps += __shfl_xor_sync(0xffffffffu, ps, 2);
                    if ((lane & 3) == 0)
                        sZs[sNext * 32 + g * 16 + (wid & 1) * 8 + (lane >> 2)] = ps;
                } else {  // mem
                    float e = (lane < 18) ? __expf(r) : 0.f;
                    float E0 = __shfl_sync(0xffffffffu, e, 0);
                    float E1 = __shfl_sync(0xffffffffu, e, 1);
                    float ep = __shfl_sync(0xffffffffu, e, 2 + (lane & 15));
                    float topn = E1 * h0 + E0 * h1 + ep;          // raw, scale Zt
                    if (lane < 16) sTop[sNext * 32 + g * 16 + lane] = topn;
                    int pidx = (lane < 2) ? lane : lane + 2;
                    if (lane < 18) sPr[(ping ^ 1) * 40 + g * 20 + pidx] = e;
                    float pz = e;
                    pz += __shfl_xor_sync(0xffffffffu, pz, 1);
                    pz += __shfl_xor_sync(0xffffffffu, pz, 2);
                    if ((lane & 3) == 0) sZmP[sNext * 16 + g * 8 + (lane >> 2)] = pz;
                    topc = topn; cE0 = E0; cE1 = E1; cZp = pz;
                }
            }
            BAR_ARRIVE(2 + sNext, 512);   // slot sNext ready for B (after own writes)
            BAR_SYNC(1, 256);             // A-internal step barrier
        }

        // epilogue: apply probs_{S-1} -> stack_S  (probs in sPr[0], Z in slot 0)
        if (isUpdate) {
            stack_update(sPr + 0 * 40 + g * 20, sZmP + 0 * 16 + g * 8,
                         sStack + 0 * 2048 + g * 1024,
                         sStack + 1 * 2048 + g * 1024, lane);
        }
    }
    __syncthreads();

    // ---- finals ----
    const size_t fsOff = (size_t)B_TOT * SEQ * 128;
    const size_t stOff = fsOff + (size_t)B_TOT * 64 * 16;
    for (int i = tid; i < 2048; i += NTHREADS) {
        int gg = i >> 10, r = i & 1023;
        out[fsOff + (size_t)(b0 + gg) * 1024 + r] = sStack[2048 + i];
    }
    if (tid < 128) {
        int gg = tid >> 6;
        float zs = 0.f;
        for (int j = 0; j < 16; j++) zs += sZs[gg * 16 + j];   // slot 0
        out[stOff + (size_t)(b0 + gg) * 64 + (tid & 63)] =
            sSt[tid] * __fdividef(1.f, zs);                    // slot 0
    }
}

extern "C" void kernel_launch(void* const* d_in, const int* in_sizes, int n_in,
                              void* d_out, int out_size)
{
    const int*   x       = (const int*)  d_in[0];
    const float* embed   = (const float*)d_in[1];
    const float* w_state = (const float*)d_in[2];
    const float* b_state = (const float*)d_in[3];
    const float* w_top   = (const float*)d_in[4];
    const float* b_top   = (const float*)d_in[5];
    const float* w_mem   = (const float*)d_in[6];
    const float* b_mem   = (const float*)d_in[7];
    const float* w_buf   = (const float*)d_in[8];
    const float* b_buf   = (const float*)d_in[9];
    const float* w_st    = (const float*)d_in[10];
    const float* b_st    = (const float*)d_in[11];
    float* out = (float*)d_out;

    precompute_kernel<<<NOUT, 448>>>(embed, w_state, b_state, w_top, b_top,
                                     w_mem, b_mem, w_buf, b_buf, w_st, b_st);

    cudaFuncSetAttribute(stackrnn_kernel,
                         cudaFuncAttributeMaxDynamicSharedMemorySize,
                         SMEM_FLOATS * sizeof(float));
    stackrnn_kernel<<<B_TOT / 2, NTHREADS, SMEM_FLOATS * sizeof(float)>>>(x, out);
}